// round 17
// baseline (speedup 1.0000x reference)
#include <cuda_runtime.h>
#include <cuda_fp16.h>
#include <cooperative_groups.h>
#include <math.h>

namespace cg = cooperative_groups;

#define N_NODES 50000
#define N_EDGES 1600000
#define CH 128
#define CH4 (CH / 4)
#define HEADS 4
#define NEG_SLOPE 0.2f
#define N_ROOTS 64
#define ACT_MAX 4096
#define CAP 128
#define NMASK ((N_NODES + 31) / 32 + 1)
#define DENSE_MASK 0x1FFFu

#define GM 128
#define SX 136
#define GEMM_SMEM ((GM * SX + CH * SX) * 2)
#define TAIL_BLOCKS 128        // <= 148 SMs: co-resident even with 68KB smem

// ---------------- persistent device scratch ----------------
__device__ uint4    g_hh[(size_t)N_NODES * 16];
__device__ float4   g_feat4[(size_t)N_NODES * CH4];
__device__ float    g_as[N_NODES * HEADS];
__device__ float    g_ad[N_NODES * HEADS];
__device__ __half   g_W16[2][CH * CH];
__device__ unsigned g_rootmask[NMASK];
__device__ unsigned g_actmask[NMASK];
__device__ unsigned g_dense[N_NODES];
__device__ int      g_active[ACT_MAX];
__device__ int      g_cnt[ACT_MAX];
__device__ int      g_slots[(size_t)ACT_MAX * CAP];
__device__ int      g_nactive;
__device__ int      g_ver;

// ---------------- W fp16 transpose conversion ----------------
__global__ void wconvert_kernel(const float* __restrict__ W1,
                                const float* __restrict__ W2) {
    int idx = blockIdx.x * blockDim.x + threadIdx.x;
    if (idx < CH * CH) {
        int n = idx >> 7, k = idx & 127;
        g_W16[0][idx] = __float2half(W1[k * CH + n]);
        g_W16[1][idx] = __float2half(W2[k * CH + n]);
    }
}

// ---------------- epoch-versioned claim ----------------
__device__ __forceinline__ void claim_active(int node, unsigned ver) {
    unsigned tag = ver << 13;
    unsigned cur = g_dense[node];
    while ((cur >> 13) != ver) {
        unsigned old = atomicCAS(&g_dense[node], cur, tag | DENSE_MASK);
        if (old == cur) {
            int p = atomicAdd(&g_nactive, 1);
            if (p < ACT_MAX) {
                g_active[p] = node;
                g_slots[(size_t)p * CAP] = node;
                g_cnt[p] = 1;
                atomicOr(&g_actmask[node >> 5], 1u << (node & 31));
                g_dense[node] = tag | (unsigned)(p + 1);
            }
            return;
        }
        cur = old;
    }
}

// ---------------- fused init + root marking ----------------
__global__ void init_mark_kernel(const int* __restrict__ roots) {
    __shared__ int sver;
    int t = threadIdx.x;
    if (t == 0) {
        int v = g_ver + 1;
        if (v > 0x7FFFF) v = 1;
        g_ver = v;
        sver = v;
        g_nactive = 0;
    }
    __syncthreads();
    unsigned ver = (unsigned)sver;
    for (int i = t; i < NMASK; i += blockDim.x) { g_rootmask[i] = 0u; g_actmask[i] = 0u; }
    __syncthreads();
    if (t < N_ROOTS) {
        int r = roots[t];
        atomicOr(&g_rootmask[r >> 5], 1u << (r & 31));
        claim_active(r, ver);
    }
}

// ---------------- discover (PDL, dst prefetch) ----------------
__global__ void discover_kernel(const int* __restrict__ ei) {
    int e8 = blockIdx.x * blockDim.x + threadIdx.x;
    bool havework = (e8 < N_EDGES / 8);
    int4 d0 = make_int4(0, 0, 0, 0), d1 = make_int4(0, 0, 0, 0);
    if (havework) {
        const int4* dst4 = (const int4*)(ei + N_EDGES);
        d0 = dst4[2 * e8];
        d1 = dst4[2 * e8 + 1];
    }
    cudaGridDependencySynchronize();
    if (!havework) return;
    unsigned ver = (unsigned)g_ver;
    int dv[8] = {d0.x, d0.y, d0.z, d0.w, d1.x, d1.y, d1.z, d1.w};
#pragma unroll
    for (int k = 0; k < 8; k++) {
        int dst = dv[k];
        if ((__ldg(&g_rootmask[dst >> 5]) >> (dst & 31)) & 1u) {
            claim_active(ei[8 * e8 + k], ver);
        }
    }
}

// ---------------- scatter (PDL, dst prefetch) ----------------
__global__ void scatter_kernel(const int* __restrict__ ei) {
    int e8 = blockIdx.x * blockDim.x + threadIdx.x;
    bool havework = (e8 < N_EDGES / 8);
    int4 d0 = make_int4(0, 0, 0, 0), d1 = make_int4(0, 0, 0, 0);
    if (havework) {
        const int4* dst4 = (const int4*)(ei + N_EDGES);
        d0 = dst4[2 * e8];
        d1 = dst4[2 * e8 + 1];
    }
    cudaGridDependencySynchronize();
    if (!havework) return;
    unsigned ver = (unsigned)g_ver;
    int dv[8] = {d0.x, d0.y, d0.z, d0.w, d1.x, d1.y, d1.z, d1.w};
#pragma unroll
    for (int k = 0; k < 8; k++) {
        int dst = dv[k];
        if ((__ldg(&g_actmask[dst >> 5]) >> (dst & 31)) & 1u) {
            unsigned di = g_dense[dst];
            unsigned dn = di & DENSE_MASK;
            if ((di >> 13) == ver && dn > 0u && dn < DENSE_MASK) {
                int src = ei[8 * e8 + k];
                int pos = atomicAdd(&g_cnt[dn - 1], 1);
                if (pos < CAP) g_slots[(size_t)(dn - 1) * CAP + pos] = src;
            }
        }
    }
}

// ---------------- shared GEMM core (128 rows x 128 cols, HMMA) ----------------
// Caller stages xs; this stages W and runs MMA + epilogue.
__device__ __forceinline__ void gemm_core(__half* xs, __half* Wt,
                                          const uint4* __restrict__ Wg,
                                          const float* __restrict__ asrc,
                                          const float* __restrict__ adst,
                                          int row0, int nact, int use_act) {
    int tid = threadIdx.x;
    int lane = tid & 31;
    int w = tid >> 5;

#pragma unroll
    for (int i = 0; i < 8; i++) {
        int idx8 = tid + 256 * i;
        int n  = idx8 >> 4;
        int k0 = (idx8 & 15) * 8;
        *(uint4*)(Wt + n * SX + k0) = Wg[idx8];
    }
    __syncthreads();

    int qr = lane >> 2;
    int qc = (lane & 3) * 2;
    int wrow = w * 16;

    float acc[16][4];
#pragma unroll
    for (int nt = 0; nt < 16; nt++) {
        acc[nt][0] = acc[nt][1] = acc[nt][2] = acc[nt][3] = 0.f;
    }

#pragma unroll
    for (int kc = 0; kc < CH; kc += 16) {
        unsigned a0 = *(const unsigned*)(xs + (wrow + qr) * SX + kc + qc);
        unsigned a1 = *(const unsigned*)(xs + (wrow + qr + 8) * SX + kc + qc);
        unsigned a2 = *(const unsigned*)(xs + (wrow + qr) * SX + kc + qc + 8);
        unsigned a3 = *(const unsigned*)(xs + (wrow + qr + 8) * SX + kc + qc + 8);
#pragma unroll
        for (int nt = 0; nt < 16; nt++) {
            int n = nt * 8 + qr;
            unsigned b0 = *(const unsigned*)(Wt + n * SX + kc + qc);
            unsigned b1 = *(const unsigned*)(Wt + n * SX + kc + qc + 8);
            asm volatile(
                "mma.sync.aligned.m16n8k16.row.col.f32.f16.f16.f32 "
                "{%0,%1,%2,%3}, {%4,%5,%6,%7}, {%8,%9}, {%0,%1,%2,%3};"
                : "+f"(acc[nt][0]), "+f"(acc[nt][1]), "+f"(acc[nt][2]), "+f"(acc[nt][3])
                : "r"(a0), "r"(a1), "r"(a2), "r"(a3), "r"(b0), "r"(b1));
        }
    }

    int pos0 = row0 + wrow + qr;
    int pos1 = pos0 + 8;
    int ok0 = pos0 < nact, ok1 = pos1 < nact;
    int gr0 = ok0 ? (use_act ? g_active[pos0] : pos0) : 0;
    int gr1 = ok1 ? (use_act ? g_active[pos1] : pos1) : 0;

    float s0[HEADS], d0[HEADS], s1[HEADS], d1[HEADS];
#pragma unroll
    for (int h = 0; h < HEADS; h++) { s0[h] = d0[h] = s1[h] = d1[h] = 0.f; }

#pragma unroll
    for (int nt = 0; nt < 16; nt++) {
        float2 a_s = *(const float2*)(asrc + nt * 8 + qc);
        float2 a_d = *(const float2*)(adst + nt * 8 + qc);
        int h = nt >> 2;
        s0[h] += acc[nt][0] * a_s.x + acc[nt][1] * a_s.y;
        d0[h] += acc[nt][0] * a_d.x + acc[nt][1] * a_d.y;
        s1[h] += acc[nt][2] * a_s.x + acc[nt][3] * a_s.y;
        d1[h] += acc[nt][2] * a_d.x + acc[nt][3] * a_d.y;
        if (ok0) {
            __half2 p = __floats2half2_rn(acc[nt][0], acc[nt][1]);
            ((unsigned*)g_hh)[(size_t)gr0 * 64 + nt * 4 + (lane & 3)] = *(unsigned*)&p;
        }
        if (ok1) {
            __half2 p = __floats2half2_rn(acc[nt][2], acc[nt][3]);
            ((unsigned*)g_hh)[(size_t)gr1 * 64 + nt * 4 + (lane & 3)] = *(unsigned*)&p;
        }
    }
#pragma unroll
    for (int h = 0; h < HEADS; h++) {
        s0[h] += __shfl_xor_sync(0xffffffffu, s0[h], 1);
        s0[h] += __shfl_xor_sync(0xffffffffu, s0[h], 2);
        d0[h] += __shfl_xor_sync(0xffffffffu, d0[h], 1);
        d0[h] += __shfl_xor_sync(0xffffffffu, d0[h], 2);
        s1[h] += __shfl_xor_sync(0xffffffffu, s1[h], 1);
        s1[h] += __shfl_xor_sync(0xffffffffu, s1[h], 2);
        d1[h] += __shfl_xor_sync(0xffffffffu, d1[h], 1);
        d1[h] += __shfl_xor_sync(0xffffffffu, d1[h], 2);
    }
    if ((lane & 3) == 0) {
#pragma unroll
        for (int h = 0; h < HEADS; h++) {
            if (ok0) { g_as[gr0 * HEADS + h] = s0[h]; g_ad[gr0 * HEADS + h] = d0[h]; }
            if (ok1) { g_as[gr1 * HEADS + h] = s1[h]; g_ad[gr1 * HEADS + h] = d1[h]; }
        }
    }
}

// ---------------- gemm1 (full graph, PDL over wconvert) ----------------
__global__ __launch_bounds__(256) void gemm1_kernel(
        const float* __restrict__ Xin,
        const float* __restrict__ asrc,
        const float* __restrict__ adst) {
    extern __shared__ __half smh[];
    __half* xs = smh;
    __half* Wt = smh + GM * SX;
    int tid = threadIdx.x;
    int row0 = blockIdx.x * GM;

    // stage x (independent of wconvert)
#pragma unroll
    for (int i = 0; i < 16; i++) {
        int idx = tid + 256 * i;
        int r = idx >> 5, k4 = idx & 31;
        int pos = row0 + r;
        float4 v = make_float4(0.f, 0.f, 0.f, 0.f);
        if (pos < N_NODES) {
            v = *(const float4*)(Xin + (size_t)pos * CH + 4 * k4);
        }
        *(__half2*)(xs + r * SX + 4 * k4)     = __floats2half2_rn(v.x, v.y);
        *(__half2*)(xs + r * SX + 4 * k4 + 2) = __floats2half2_rn(v.z, v.w);
    }
    cudaGridDependencySynchronize();
    gemm_core(xs, Wt, (const uint4*)g_W16[0], asrc, adst, row0, N_NODES, 0);
}

// ---------------- aggregation core: warp/node, depth-2 pipelined ----------------
struct EdgeState { float as; uint4 ha, hb; };

__device__ __forceinline__ void load_edge(const int* __restrict__ slots, int e,
                                          int head, int j, EdgeState& st) {
    int s = slots[e];
    st.as = g_as[s * HEADS + head];
    st.ha = g_hh[(size_t)s * 16 + 2 * j];
    st.hb = g_hh[(size_t)s * 16 + 2 * j + 1];
}

__device__ __forceinline__ void aggregate_node(int node, int di, int lane,
                                               const float* __restrict__ bias,
                                               float* __restrict__ outp) {
    int g = lane >> 3;
    int j = lane & 7;
    int head = j >> 1;

    float ad = g_ad[node * HEADS + head];
    const int* slots = g_slots + (size_t)di * CAP;
    int cnt = g_cnt[di];
    if (cnt > CAP) cnt = CAP;

    float dsum = 0.0f;
    float acc[16];
#pragma unroll
    for (int i = 0; i < 16; i++) acc[i] = 0.0f;

    EdgeState a = {}, b = {};
    int e = g;
    if (e < cnt)     load_edge(slots, e, head, j, a);
    if (e + 4 < cnt) load_edge(slots, e + 4, head, j, b);

    while (e < cnt) {
        EdgeState n = {};
        if (e + 8 < cnt) load_edge(slots, e + 8, head, j, n);

        float v = a.as + ad;
        v = fmaxf(v, NEG_SLOPE * v);
        float w = __expf(v);
        float2 f;
        f = __half22float2(*(__half2*)&a.ha.x); acc[0]  = fmaf(w, f.x, acc[0]);  acc[1]  = fmaf(w, f.y, acc[1]);
        f = __half22float2(*(__half2*)&a.ha.y); acc[2]  = fmaf(w, f.x, acc[2]);  acc[3]  = fmaf(w, f.y, acc[3]);
        f = __half22float2(*(__half2*)&a.ha.z); acc[4]  = fmaf(w, f.x, acc[4]);  acc[5]  = fmaf(w, f.y, acc[5]);
        f = __half22float2(*(__half2*)&a.ha.w); acc[6]  = fmaf(w, f.x, acc[6]);  acc[7]  = fmaf(w, f.y, acc[7]);
        f = __half22float2(*(__half2*)&a.hb.x); acc[8]  = fmaf(w, f.x, acc[8]);  acc[9]  = fmaf(w, f.y, acc[9]);
        f = __half22float2(*(__half2*)&a.hb.y); acc[10] = fmaf(w, f.x, acc[10]); acc[11] = fmaf(w, f.y, acc[11]);
        f = __half22float2(*(__half2*)&a.hb.z); acc[12] = fmaf(w, f.x, acc[12]); acc[13] = fmaf(w, f.y, acc[13]);
        f = __half22float2(*(__half2*)&a.hb.w); acc[14] = fmaf(w, f.x, acc[14]); acc[15] = fmaf(w, f.y, acc[15]);
        dsum += w;

        a = b; b = n; e += 4;
    }

    dsum += __shfl_xor_sync(0xffffffffu, dsum, 8);
    dsum += __shfl_xor_sync(0xffffffffu, dsum, 16);
#pragma unroll
    for (int i = 0; i < 16; i++) {
        acc[i] += __shfl_xor_sync(0xffffffffu, acc[i], 8);
        acc[i] += __shfl_xor_sync(0xffffffffu, acc[i], 16);
    }
    float inv = 1.0f / (dsum + 1e-16f);

    int c0 = 16 * j + 4 * g;
    float4 o;
    o.x = acc[4 * g + 0] * inv + bias[c0 + 0];
    o.y = acc[4 * g + 1] * inv + bias[c0 + 1];
    o.z = acc[4 * g + 2] * inv + bias[c0 + 2];
    o.w = acc[4 * g + 3] * inv + bias[c0 + 3];
    *(float4*)(outp + c0) = o;
}

// ---------------- fused tail: agg1 -> gemm2 -> agg2 (cooperative) ----------------
__global__ __launch_bounds__(256) void tail_coop_kernel(
        const float* __restrict__ b1,
        const float* __restrict__ a2s,
        const float* __restrict__ a2d,
        const float* __restrict__ b2,
        const int* __restrict__ roots,
        float* __restrict__ out) {
    cg::grid_group grid = cg::this_grid();
    extern __shared__ __half smh[];
    __half* xs = smh;
    __half* Wt = smh + GM * SX;

    int tid = threadIdx.x;
    int lane = tid & 31;
    int gw = (blockIdx.x * blockDim.x + tid) >> 5;      // global warp id
    int nwarps = (gridDim.x * blockDim.x) >> 5;
    int nact = g_nactive;

    // phase 1: layer-1 aggregation over active nodes (warp-strided)
    for (int idx = gw; idx < nact; idx += nwarps) {
        int node = g_active[idx];
        aggregate_node(node, idx, lane, b1, (float*)g_feat4 + (size_t)node * CH);
    }
    grid.sync();

    // phase 2: gemm2 over active nodes (first ceil(nact/GM) blocks)
    int row0 = blockIdx.x * GM;
    if (row0 < nact) {
#pragma unroll
        for (int i = 0; i < 16; i++) {
            int idx = tid + 256 * i;
            int r = idx >> 5, k4 = idx & 31;
            int pos = row0 + r;
            float4 v = make_float4(0.f, 0.f, 0.f, 0.f);
            if (pos < nact) {
                int node = g_active[pos];
                v = *(const float4*)((const float*)g_feat4 + (size_t)node * CH + 4 * k4);
                v.x = fmaxf(v.x, 0.f); v.y = fmaxf(v.y, 0.f);
                v.z = fmaxf(v.z, 0.f); v.w = fmaxf(v.w, 0.f);
            }
            *(__half2*)(xs + r * SX + 4 * k4)     = __floats2half2_rn(v.x, v.y);
            *(__half2*)(xs + r * SX + 4 * k4 + 2) = __floats2half2_rn(v.z, v.w);
        }
        gemm_core(xs, Wt, (const uint4*)g_W16[1], a2s, a2d, row0, nact, 1);
    }
    grid.sync();

    // phase 3: layer-2 aggregation for the 64 roots -> out
    if (gw < N_ROOTS) {
        int node = roots[gw];
        int di = (int)(g_dense[node] & DENSE_MASK) - 1;
        aggregate_node(node, di, lane, b2, out + (size_t)gw * CH);
    }
}

// ---------------- launch ----------------
extern "C" void kernel_launch(void* const* d_in, const int* in_sizes, int n_in,
                              void* d_out, int out_size) {
    const float* x     = (const float*)d_in[0];
    const int*   ei    = (const int*)d_in[1];
    const int*   roots = (const int*)d_in[2];
    const float* W1    = (const float*)d_in[3];
    const float* a1s   = (const float*)d_in[4];
    const float* a1d   = (const float*)d_in[5];
    const float* b1    = (const float*)d_in[6];
    const float* W2    = (const float*)d_in[7];
    const float* a2s   = (const float*)d_in[8];
    const float* a2d   = (const float*)d_in[9];
    const float* b2    = (const float*)d_in[10];
    float*       out   = (float*)d_out;

    static cudaStream_t s2 = 0;
    static cudaEvent_t evFork = 0, evJoin = 0;
    if (s2 == 0) {
        cudaStreamCreate(&s2);
        cudaEventCreateWithFlags(&evFork, cudaEventDisableTiming);
        cudaEventCreateWithFlags(&evJoin, cudaEventDisableTiming);
        cudaFuncSetAttribute(gemm1_kernel,
                             cudaFuncAttributeMaxDynamicSharedMemorySize, GEMM_SMEM);
        cudaFuncSetAttribute(tail_coop_kernel,
                             cudaFuncAttributeMaxDynamicSharedMemorySize, GEMM_SMEM);
    }

    const int T = 256;
    const int TS = 512;
    int nb_e8    = (N_EDGES / 8 + TS - 1) / TS;
    int nb_wcv   = (CH * CH + T - 1) / T;
    int nb_gemm1 = (N_NODES + GM - 1) / GM;

    cudaLaunchAttribute pdl[1];
    pdl[0].id = cudaLaunchAttributeProgrammaticStreamSerialization;
    pdl[0].val.programmaticStreamSerializationAllowed = 1;

    // side stream: wconvert, then gemm1 with PDL
    cudaEventRecord(evFork, 0);
    cudaStreamWaitEvent(s2, evFork, 0);
    wconvert_kernel<<<nb_wcv, T, 0, s2>>>(W1, W2);
    {
        cudaLaunchConfig_t cfg = {};
        cfg.gridDim = dim3(nb_gemm1); cfg.blockDim = dim3(T);
        cfg.dynamicSmemBytes = GEMM_SMEM; cfg.stream = s2;
        cfg.attrs = pdl; cfg.numAttrs = 1;
        cudaLaunchKernelEx(&cfg, gemm1_kernel, x, a1s, a1d);
    }
    cudaEventRecord(evJoin, s2);

    // main stream: init+mark, PDL discover + scatter
    init_mark_kernel<<<1, 1024>>>(roots);
    {
        cudaLaunchConfig_t cfg = {};
        cfg.gridDim = dim3(nb_e8); cfg.blockDim = dim3(TS);
        cfg.stream = 0; cfg.attrs = pdl; cfg.numAttrs = 1;
        cudaLaunchKernelEx(&cfg, discover_kernel, ei);
        cudaLaunchKernelEx(&cfg, scatter_kernel, ei);
    }

    // fused cooperative tail after cross-stream join
    cudaStreamWaitEvent(0, evJoin, 0);
    {
        cudaLaunchAttribute coop[1];
        coop[0].id = cudaLaunchAttributeCooperative;
        coop[0].val.cooperative = 1;
        cudaLaunchConfig_t cfg = {};
        cfg.gridDim = dim3(TAIL_BLOCKS); cfg.blockDim = dim3(T);
        cfg.dynamicSmemBytes = GEMM_SMEM; cfg.stream = 0;
        cfg.attrs = coop; cfg.numAttrs = 1;
        cudaLaunchKernelEx(&cfg, tail_coop_kernel, b1, a2s, a2d, b2, roots, out);
    }
}